// round 1
// baseline (speedup 1.0000x reference)
#include <cuda_runtime.h>
#include <math.h>

// GPT-2 small forward pass, fp32 baseline.
// B=2, T=1024, C=768, H=12, HD=64, L=12, V=50257.

#define Bsz 2
#define Tlen 1024
#define BT (Bsz * Tlen)      // 2048
#define C 768
#define H 12
#define HD 64
#define NL 12
#define V 50257
#define C3 (3 * C)           // 2304
#define C4 (4 * C)           // 3072
#define EPS 1e-5f

// ---------------- scratch (static device globals; no allocation) ----------------
__device__ float g_x[BT * C];      // residual stream
__device__ float g_ln[BT * C];     // layernorm output
__device__ float g_qkv[BT * C3];   // fused qkv
__device__ float g_atty[BT * C];   // attention output (pre-projection)
__device__ float g_h[BT * C4];     // fc / gelu activations

// ---------------- embedding ----------------
__global__ void embed_kernel(const int* __restrict__ idx,
                             const float* __restrict__ wte,
                             const float* __restrict__ wpe,
                             float* __restrict__ out) {
    int row = blockIdx.x;            // 0..BT-1
    int tpos = row % Tlen;
    int tok = idx[row];
    const float* we = wte + (long long)tok * C;
    const float* pe = wpe + (long long)tpos * C;
    float* o = out + (long long)row * C;
    for (int c = threadIdx.x; c < C; c += blockDim.x)
        o[c] = we[c] + pe[c];
}

// ---------------- layernorm (one block per row) ----------------
__global__ void ln_kernel(const float* __restrict__ x,
                          const float* __restrict__ w,
                          const float* __restrict__ b,
                          float* __restrict__ out) {
    __shared__ float red[256];
    __shared__ float red2[256];
    int row = blockIdx.x;
    const float* xr = x + (long long)row * C;
    float s = 0.f, sq = 0.f;
    for (int c = threadIdx.x; c < C; c += blockDim.x) {
        float v = xr[c];
        s += v; sq += v * v;
    }
    red[threadIdx.x] = s; red2[threadIdx.x] = sq;
    __syncthreads();
    for (int off = 128; off > 0; off >>= 1) {
        if (threadIdx.x < off) {
            red[threadIdx.x] += red[threadIdx.x + off];
            red2[threadIdx.x] += red2[threadIdx.x + off];
        }
        __syncthreads();
    }
    float mean = red[0] / C;
    float var = red2[0] / C - mean * mean;
    float rstd = rsqrtf(var + EPS);
    float* o = out + (long long)row * C;
    for (int c = threadIdx.x; c < C; c += blockDim.x)
        o[c] = (xr[c] - mean) * rstd * w[c] + b[c];
}

// ---------------- gelu ----------------
__device__ __forceinline__ float gelu_f(float x) {
    float x3 = x * x * x;
    return 0.5f * x * (1.f + tanhf(0.7978845608028654f * (x + 0.044715f * x3)));
}

// ---------------- SGEMM: out[M,N] = A[M,K] @ W[K,N] (+bias, epilogue) ----------------
// epi: 0 = +bias; 1 = gelu(+bias); 2 = +bias + out (residual accumulate in-place); 3 = none
__global__ void __launch_bounds__(256)
sgemm_kernel(const float* __restrict__ A, const float* __restrict__ W,
             const float* __restrict__ bias, float* __restrict__ out,
             int M, int N, int K, int epi) {
    __shared__ float As[16][64];
    __shared__ float Bs[16][64];

    int tid = threadIdx.x;
    int tx = tid & 15;        // 0..15 -> n micro
    int ty = tid >> 4;        // 0..15 -> m micro
    int m0 = blockIdx.y * 64;
    int n0 = blockIdx.x * 64;

    float acc[4][4];
#pragma unroll
    for (int i = 0; i < 4; i++)
#pragma unroll
        for (int j = 0; j < 4; j++) acc[i][j] = 0.f;

    for (int k0 = 0; k0 < K; k0 += 16) {
        // load A tile (64 rows x 16 k) transposed into As[k][m]
#pragma unroll
        for (int i = 0; i < 4; i++) {
            int id = tid + i * 256;
            int r = id >> 4, c = id & 15;
            As[c][r] = A[(long long)(m0 + r) * K + (k0 + c)];
        }
        // load W tile (16 k x 64 n)
#pragma unroll
        for (int i = 0; i < 4; i++) {
            int id = tid + i * 256;
            int r = id >> 6, c = id & 63;
            int n = n0 + c;
            Bs[r][c] = (n < N) ? W[(long long)(k0 + r) * N + n] : 0.f;
        }
        __syncthreads();

#pragma unroll
        for (int kk = 0; kk < 16; kk++) {
            float a[4], b[4];
#pragma unroll
            for (int i = 0; i < 4; i++) a[i] = As[kk][ty * 4 + i];
#pragma unroll
            for (int j = 0; j < 4; j++) b[j] = Bs[kk][tx * 4 + j];
#pragma unroll
            for (int i = 0; i < 4; i++)
#pragma unroll
                for (int j = 0; j < 4; j++) acc[i][j] += a[i] * b[j];
        }
        __syncthreads();
    }

#pragma unroll
    for (int i = 0; i < 4; i++) {
        int m = m0 + ty * 4 + i;
#pragma unroll
        for (int j = 0; j < 4; j++) {
            int n = n0 + tx * 4 + j;
            if (n < N) {
                float v = acc[i][j];
                if (epi != 3) v += bias[n];
                if (epi == 1) v = gelu_f(v);
                long long o = (long long)m * N + n;
                if (epi == 2) v += out[o];
                out[o] = v;
            }
        }
    }
}

// ---------------- fused causal attention (online softmax, one warp per query) ----------------
// qkv layout: [BT, 3C] with q = [0,C), k = [C,2C), v = [2C,3C); head h at h*HD.
// grid: (T/8, H, B), block 256 (8 warps). out: [BT, C].
__global__ void __launch_bounds__(256)
attn_kernel(const float* __restrict__ qkv, float* __restrict__ out) {
    int warp = threadIdx.x >> 5;
    int lane = threadIdx.x & 31;
    int q = blockIdx.x * 8 + warp;
    int h = blockIdx.y;
    int b = blockIdx.z;

    const float* qrow = qkv + ((long long)(b * Tlen + q) * C3) + h * HD;
    float q0 = qrow[lane];
    float q1 = qrow[lane + 32];

    float m = -INFINITY, l = 0.f, acc0 = 0.f, acc1 = 0.f;
    const float scale = 0.125f; // 1/sqrt(64)

    for (int k = 0; k <= q; k++) {
        const float* krow = qkv + ((long long)(b * Tlen + k) * C3) + C + h * HD;
        float s = q0 * krow[lane] + q1 * krow[lane + 32];
        // butterfly warp reduce -> all lanes hold the sum
#pragma unroll
        for (int off = 16; off > 0; off >>= 1)
            s += __shfl_xor_sync(0xFFFFFFFFu, s, off);
        s *= scale;

        float mn = fmaxf(m, s);
        float cscale = __expf(m - mn);   // 0 on first iter (m = -inf)
        float p = __expf(s - mn);
        const float* vrow = qkv + ((long long)(b * Tlen + k) * C3) + 2 * C + h * HD;
        l = l * cscale + p;
        acc0 = acc0 * cscale + p * vrow[lane];
        acc1 = acc1 * cscale + p * vrow[lane + 32];
        m = mn;
    }

    float inv = 1.f / l;
    float* o = out + ((long long)(b * Tlen + q) * C) + h * HD;
    o[lane] = acc0 * inv;
    o[lane + 32] = acc1 * inv;
}

// ---------------- driver ----------------
extern "C" void kernel_launch(void* const* d_in, const int* in_sizes, int n_in,
                              void* d_out, int out_size) {
    const int*   idx      = (const int*)  d_in[0];
    const float* wte      = (const float*)d_in[1];
    const float* wpe      = (const float*)d_in[2];
    const float* ln1_w    = (const float*)d_in[3];
    const float* ln1_b    = (const float*)d_in[4];
    const float* attn_w   = (const float*)d_in[5];
    const float* attn_b   = (const float*)d_in[6];
    const float* proj_w   = (const float*)d_in[7];
    const float* proj_b   = (const float*)d_in[8];
    const float* ln2_w    = (const float*)d_in[9];
    const float* ln2_b    = (const float*)d_in[10];
    const float* fc_w     = (const float*)d_in[11];
    const float* fc_b     = (const float*)d_in[12];
    const float* fcproj_w = (const float*)d_in[13];
    const float* fcproj_b = (const float*)d_in[14];
    const float* lnf_w    = (const float*)d_in[15];
    const float* lnf_b    = (const float*)d_in[16];
    const float* lm_head  = (const float*)d_in[17];
    float* out = (float*)d_out;

    float *x, *ln, *qkv, *atty, *hbuf;
    cudaGetSymbolAddress((void**)&x,    g_x);
    cudaGetSymbolAddress((void**)&ln,   g_ln);
    cudaGetSymbolAddress((void**)&qkv,  g_qkv);
    cudaGetSymbolAddress((void**)&atty, g_atty);
    cudaGetSymbolAddress((void**)&hbuf, g_h);

    embed_kernel<<<BT, 256>>>(idx, wte, wpe, x);

    for (int l = 0; l < NL; l++) {
        ln_kernel<<<BT, 256>>>(x, ln1_w + l * C, ln1_b + l * C, ln);
        sgemm_kernel<<<dim3(C3 / 64, BT / 64), 256>>>(
            ln, attn_w + (long long)l * C * C3, attn_b + l * C3, qkv, BT, C3, C, 0);
        attn_kernel<<<dim3(Tlen / 8, H, Bsz), 256>>>(qkv, atty);
        sgemm_kernel<<<dim3(C / 64, BT / 64), 256>>>(
            atty, proj_w + (long long)l * C * C, proj_b + l * C, x, BT, C, C, 2);
        ln_kernel<<<BT, 256>>>(x, ln2_w + l * C, ln2_b + l * C, ln);
        sgemm_kernel<<<dim3(C4 / 64, BT / 64), 256>>>(
            ln, fc_w + (long long)l * C * C4, fc_b + l * C4, hbuf, BT, C4, C, 1);
        sgemm_kernel<<<dim3(C / 64, BT / 64), 256>>>(
            hbuf, fcproj_w + (long long)l * C4 * C, fcproj_b + l * C, x, BT, C, C4, 2);
    }

    ln_kernel<<<BT, 256>>>(x, lnf_w, lnf_b, ln);
    sgemm_kernel<<<dim3((V + 63) / 64, BT / 64), 256>>>(
        ln, lm_head, (const float*)nullptr, out, BT, V, C, 3);
}

// round 2
// speedup vs baseline: 1.8533x; 1.8533x over previous
#include <cuda_runtime.h>
#include <math.h>

// GPT-2 small forward: tf32 tensor-core GEMMs + fp32 attention/LN.
// B=2, T=1024, C=768, H=12, HD=64, L=12, V=50257.

#define Bsz 2
#define Tlen 1024
#define BT (Bsz * Tlen)      // 2048
#define C 768
#define H 12
#define HD 64
#define NL 12
#define V 50257
#define C3 (3 * C)           // 2304
#define C4 (4 * C)           // 3072
#define EPS 1e-5f

// ---------------- scratch ----------------
__device__ float g_x[BT * C];
__device__ float g_ln[BT * C];
__device__ float g_qkv[BT * C3];
__device__ float g_atty[BT * C];
__device__ float g_h[BT * C4];

// ---------------- embedding ----------------
__global__ void embed_kernel(const int* __restrict__ idx,
                             const float* __restrict__ wte,
                             const float* __restrict__ wpe,
                             float* __restrict__ out) {
    int row = blockIdx.x;
    int tpos = row % Tlen;
    int tok = idx[row];
    const float* we = wte + (long long)tok * C;
    const float* pe = wpe + (long long)tpos * C;
    float* o = out + (long long)row * C;
    for (int c = threadIdx.x; c < C; c += blockDim.x)
        o[c] = we[c] + pe[c];
}

// ---------------- layernorm ----------------
__global__ void ln_kernel(const float* __restrict__ x,
                          const float* __restrict__ w,
                          const float* __restrict__ b,
                          float* __restrict__ out) {
    __shared__ float red[256];
    __shared__ float red2[256];
    int row = blockIdx.x;
    const float* xr = x + (long long)row * C;
    float s = 0.f, sq = 0.f;
    for (int c = threadIdx.x; c < C; c += blockDim.x) {
        float v = xr[c];
        s += v; sq += v * v;
    }
    red[threadIdx.x] = s; red2[threadIdx.x] = sq;
    __syncthreads();
    for (int off = 128; off > 0; off >>= 1) {
        if (threadIdx.x < off) {
            red[threadIdx.x] += red[threadIdx.x + off];
            red2[threadIdx.x] += red2[threadIdx.x + off];
        }
        __syncthreads();
    }
    float mean = red[0] / C;
    float var = red2[0] / C - mean * mean;
    float rstd = rsqrtf(var + EPS);
    float* o = out + (long long)row * C;
    for (int c = threadIdx.x; c < C; c += blockDim.x)
        o[c] = (xr[c] - mean) * rstd * w[c] + b[c];
}

// ---------------- gelu ----------------
__device__ __forceinline__ float gelu_f(float x) {
    float x3 = x * x * x;
    return 0.5f * x * (1.f + tanhf(0.7978845608028654f * (x + 0.044715f * x3)));
}

__device__ __forceinline__ unsigned tf32_of(float f) {
    unsigned u;
    asm("cvt.rna.tf32.f32 %0, %1;" : "=r"(u) : "f"(f));
    return u;
}

// ---------------- tf32 tensor-core GEMM ----------------
// out[M,N] = A[M,K] @ W[K,N]; epi: 0=+bias, 1=gelu(+bias), 2=+bias+out(residual), 3=none
// Block tile 128x128, K-tile 16, 256 threads (8 warps: 2 in M x 4 in N, each 64x32).
#define ASTR 20      // 16 + 4 pad
#define BSTR 136     // 128 + 8 pad

__global__ void __launch_bounds__(256)
tgemm_kernel(const float* __restrict__ A, const float* __restrict__ W,
             const float* __restrict__ bias, float* __restrict__ out,
             int M, int N, int K, int epi) {
    __shared__ unsigned As[2][128 * ASTR];
    __shared__ unsigned Bs[2][16 * BSTR];

    int tid = threadIdx.x;
    int warp = tid >> 5, lane = tid & 31;
    int g = lane >> 2, tig = lane & 3;
    int wm = (warp & 1) * 64;
    int wn = (warp >> 1) * 32;
    int m0 = blockIdx.y * 128;
    int n0 = blockIdx.x * 128;

    float c[4][4][4];
#pragma unroll
    for (int mi = 0; mi < 4; mi++)
#pragma unroll
        for (int nj = 0; nj < 4; nj++)
#pragma unroll
            for (int r = 0; r < 4; r++) c[mi][nj][r] = 0.f;

    // global load coords
    int a_m = tid >> 2;              // 0..63 (and +64)
    int a_k = (tid & 3) * 4;
    int b_k = tid >> 5;              // 0..7 (and +8)
    int b_n = (tid & 31) * 4;

    float4 ra0, ra1;
    float rb[2][4];

    // ---- prologue: load tile 0 ----
    {
        ra0 = *(const float4*)(A + (long long)(m0 + a_m) * K + a_k);
        ra1 = *(const float4*)(A + (long long)(m0 + a_m + 64) * K + a_k);
#pragma unroll
        for (int i = 0; i < 2; i++) {
            const float* wr = W + (long long)(b_k + 8 * i) * N;
#pragma unroll
            for (int j = 0; j < 4; j++) {
                int col = n0 + b_n + j;
                rb[i][j] = (col < N) ? wr[col] : 0.f;
            }
        }
        unsigned* as = As[0];
        as[a_m * ASTR + a_k + 0] = tf32_of(ra0.x);
        as[a_m * ASTR + a_k + 1] = tf32_of(ra0.y);
        as[a_m * ASTR + a_k + 2] = tf32_of(ra0.z);
        as[a_m * ASTR + a_k + 3] = tf32_of(ra0.w);
        as[(a_m + 64) * ASTR + a_k + 0] = tf32_of(ra1.x);
        as[(a_m + 64) * ASTR + a_k + 1] = tf32_of(ra1.y);
        as[(a_m + 64) * ASTR + a_k + 2] = tf32_of(ra1.z);
        as[(a_m + 64) * ASTR + a_k + 3] = tf32_of(ra1.w);
        unsigned* bs = Bs[0];
#pragma unroll
        for (int i = 0; i < 2; i++)
#pragma unroll
            for (int j = 0; j < 4; j++)
                bs[(b_k + 8 * i) * BSTR + b_n + j] = tf32_of(rb[i][j]);
    }
    __syncthreads();

    int nk = K / 16;
    for (int kt = 0; kt < nk; kt++) {
        int cur = kt & 1, nxt = cur ^ 1;
        bool more = (kt + 1 < nk);
        if (more) {
            int k0 = (kt + 1) * 16;
            ra0 = *(const float4*)(A + (long long)(m0 + a_m) * K + k0 + a_k);
            ra1 = *(const float4*)(A + (long long)(m0 + a_m + 64) * K + k0 + a_k);
#pragma unroll
            for (int i = 0; i < 2; i++) {
                const float* wr = W + (long long)(k0 + b_k + 8 * i) * N;
#pragma unroll
                for (int j = 0; j < 4; j++) {
                    int col = n0 + b_n + j;
                    rb[i][j] = (col < N) ? wr[col] : 0.f;
                }
            }
        }

        const unsigned* as = As[cur];
        const unsigned* bs = Bs[cur];
#pragma unroll
        for (int kk = 0; kk < 2; kk++) {
            unsigned af[4][4], bf[4][2];
#pragma unroll
            for (int mi = 0; mi < 4; mi++) {
                int r = wm + mi * 16 + g;
                af[mi][0] = as[r * ASTR + kk * 8 + tig];
                af[mi][1] = as[(r + 8) * ASTR + kk * 8 + tig];
                af[mi][2] = as[r * ASTR + kk * 8 + tig + 4];
                af[mi][3] = as[(r + 8) * ASTR + kk * 8 + tig + 4];
            }
#pragma unroll
            for (int nj = 0; nj < 4; nj++) {
                int col = wn + nj * 8 + g;
                bf[nj][0] = bs[(kk * 8 + tig) * BSTR + col];
                bf[nj][1] = bs[(kk * 8 + tig + 4) * BSTR + col];
            }
#pragma unroll
            for (int mi = 0; mi < 4; mi++)
#pragma unroll
                for (int nj = 0; nj < 4; nj++)
                    asm volatile(
                        "mma.sync.aligned.m16n8k8.row.col.f32.tf32.tf32.f32 "
                        "{%0,%1,%2,%3},{%4,%5,%6,%7},{%8,%9},{%0,%1,%2,%3};\n"
                        : "+f"(c[mi][nj][0]), "+f"(c[mi][nj][1]),
                          "+f"(c[mi][nj][2]), "+f"(c[mi][nj][3])
                        : "r"(af[mi][0]), "r"(af[mi][1]), "r"(af[mi][2]), "r"(af[mi][3]),
                          "r"(bf[nj][0]), "r"(bf[nj][1]));
        }

        if (more) {
            unsigned* asn = As[nxt];
            asn[a_m * ASTR + a_k + 0] = tf32_of(ra0.x);
            asn[a_m * ASTR + a_k + 1] = tf32_of(ra0.y);
            asn[a_m * ASTR + a_k + 2] = tf32_of(ra0.z);
            asn[a_m * ASTR + a_k + 3] = tf32_of(ra0.w);
            asn[(a_m + 64) * ASTR + a_k + 0] = tf32_of(ra1.x);
            asn[(a_m + 64) * ASTR + a_k + 1] = tf32_of(ra1.y);
            asn[(a_m + 64) * ASTR + a_k + 2] = tf32_of(ra1.z);
            asn[(a_m + 64) * ASTR + a_k + 3] = tf32_of(ra1.w);
            unsigned* bsn = Bs[nxt];
#pragma unroll
            for (int i = 0; i < 2; i++)
#pragma unroll
                for (int j = 0; j < 4; j++)
                    bsn[(b_k + 8 * i) * BSTR + b_n + j] = tf32_of(rb[i][j]);
        }
        __syncthreads();
    }

    // ---- epilogue ----
#pragma unroll
    for (int mi = 0; mi < 4; mi++) {
        int r0 = m0 + wm + mi * 16 + g;
#pragma unroll
        for (int nj = 0; nj < 4; nj++) {
            int col = n0 + wn + nj * 8 + 2 * tig;
#pragma unroll
            for (int half = 0; half < 2; half++) {
                int rr = r0 + half * 8;
#pragma unroll
                for (int jj = 0; jj < 2; jj++) {
                    int cc = col + jj;
                    if (cc < N) {
                        float v = c[mi][nj][half * 2 + jj];
                        if (epi != 3) v += bias[cc];
                        if (epi == 1) v = gelu_f(v);
                        long long o = (long long)rr * N + cc;
                        if (epi == 2) v += out[o];
                        out[o] = v;
                    }
                }
            }
        }
    }
}

// ---------------- fused causal attention (online softmax, one warp per query) ----------------
__global__ void __launch_bounds__(256)
attn_kernel(const float* __restrict__ qkv, float* __restrict__ out) {
    int warp = threadIdx.x >> 5;
    int lane = threadIdx.x & 31;
    int q = blockIdx.x * 8 + warp;
    int h = blockIdx.y;
    int b = blockIdx.z;

    const float* qrow = qkv + ((long long)(b * Tlen + q) * C3) + h * HD;
    float q0 = qrow[lane];
    float q1 = qrow[lane + 32];

    float m = -INFINITY, l = 0.f, acc0 = 0.f, acc1 = 0.f;
    const float scale = 0.125f;

    for (int k = 0; k <= q; k++) {
        const float* krow = qkv + ((long long)(b * Tlen + k) * C3) + C + h * HD;
        float s = q0 * krow[lane] + q1 * krow[lane + 32];
#pragma unroll
        for (int off = 16; off > 0; off >>= 1)
            s += __shfl_xor_sync(0xFFFFFFFFu, s, off);
        s *= scale;

        float mn = fmaxf(m, s);
        float cscale = __expf(m - mn);
        float p = __expf(s - mn);
        const float* vrow = qkv + ((long long)(b * Tlen + k) * C3) + 2 * C + h * HD;
        l = l * cscale + p;
        acc0 = acc0 * cscale + p * vrow[lane];
        acc1 = acc1 * cscale + p * vrow[lane + 32];
        m = mn;
    }

    float inv = 1.f / l;
    float* o = out + ((long long)(b * Tlen + q) * C) + h * HD;
    o[lane] = acc0 * inv;
    o[lane + 32] = acc1 * inv;
}

// ---------------- driver ----------------
extern "C" void kernel_launch(void* const* d_in, const int* in_sizes, int n_in,
                              void* d_out, int out_size) {
    const int*   idx      = (const int*)  d_in[0];
    const float* wte      = (const float*)d_in[1];
    const float* wpe      = (const float*)d_in[2];
    const float* ln1_w    = (const float*)d_in[3];
    const float* ln1_b    = (const float*)d_in[4];
    const float* attn_w   = (const float*)d_in[5];
    const float* attn_b   = (const float*)d_in[6];
    const float* proj_w   = (const float*)d_in[7];
    const float* proj_b   = (const float*)d_in[8];
    const float* ln2_w    = (const float*)d_in[9];
    const float* ln2_b    = (const float*)d_in[10];
    const float* fc_w     = (const float*)d_in[11];
    const float* fc_b     = (const float*)d_in[12];
    const float* fcproj_w = (const float*)d_in[13];
    const float* fcproj_b = (const float*)d_in[14];
    const float* lnf_w    = (const float*)d_in[15];
    const float* lnf_b    = (const float*)d_in[16];
    const float* lm_head  = (const float*)d_in[17];
    float* out = (float*)d_out;

    float *x, *ln, *qkv, *atty, *hbuf;
    cudaGetSymbolAddress((void**)&x,    g_x);
    cudaGetSymbolAddress((void**)&ln,   g_ln);
    cudaGetSymbolAddress((void**)&qkv,  g_qkv);
    cudaGetSymbolAddress((void**)&atty, g_atty);
    cudaGetSymbolAddress((void**)&hbuf, g_h);

    embed_kernel<<<BT, 256>>>(idx, wte, wpe, x);

    for (int l = 0; l < NL; l++) {
        ln_kernel<<<BT, 256>>>(x, ln1_w + l * C, ln1_b + l * C, ln);
        tgemm_kernel<<<dim3(C3 / 128, BT / 128), 256>>>(
            ln, attn_w + (long long)l * C * C3, attn_b + l * C3, qkv, BT, C3, C, 0);
        attn_kernel<<<dim3(Tlen / 8, H, Bsz), 256>>>(qkv, atty);
        tgemm_kernel<<<dim3(C / 128, BT / 128), 256>>>(
            atty, proj_w + (long long)l * C * C, proj_b + l * C, x, BT, C, C, 2);
        ln_kernel<<<BT, 256>>>(x, ln2_w + l * C, ln2_b + l * C, ln);
        tgemm_kernel<<<dim3(C4 / 128, BT / 128), 256>>>(
            ln, fc_w + (long long)l * C * C4, fc_b + l * C4, hbuf, BT, C4, C, 1);
        tgemm_kernel<<<dim3(C / 128, BT / 128), 256>>>(
            hbuf, fcproj_w + (long long)l * C4 * C, fcproj_b + l * C, x, BT, C, C4, 2);
    }

    ln_kernel<<<BT, 256>>>(x, lnf_w, lnf_b, ln);
    tgemm_kernel<<<dim3((V + 127) / 128, BT / 128), 256>>>(
        ln, lm_head, (const float*)nullptr, out, BT, V, C, 3);
}

// round 3
// speedup vs baseline: 3.4495x; 1.8613x over previous
#include <cuda_runtime.h>
#include <math.h>

// GPT-2 small forward: tf32 tensor-core GEMMs + tiled fp32 flash attention.
// B=2, T=1024, C=768, H=12, HD=64, L=12, V=50257.

#define Bsz 2
#define Tlen 1024
#define BT (Bsz * Tlen)      // 2048
#define C 768
#define H 12
#define HD 64
#define NL 12
#define V 50257
#define C3 (3 * C)           // 2304
#define C4 (4 * C)           // 3072
#define EPS 1e-5f

// ---------------- scratch ----------------
__device__ float g_x[BT * C];
__device__ float g_ln[BT * C];
__device__ float g_qkv[BT * C3];
__device__ float g_atty[BT * C];
__device__ float g_h[BT * C4];

// ---------------- embedding ----------------
__global__ void embed_kernel(const int* __restrict__ idx,
                             const float* __restrict__ wte,
                             const float* __restrict__ wpe,
                             float* __restrict__ out) {
    int row = blockIdx.x;
    int tpos = row % Tlen;
    int tok = idx[row];
    const float* we = wte + (long long)tok * C;
    const float* pe = wpe + (long long)tpos * C;
    float* o = out + (long long)row * C;
    for (int c = threadIdx.x; c < C; c += blockDim.x)
        o[c] = we[c] + pe[c];
}

// ---------------- layernorm ----------------
__global__ void ln_kernel(const float* __restrict__ x,
                          const float* __restrict__ w,
                          const float* __restrict__ b,
                          float* __restrict__ out) {
    __shared__ float red[256];
    __shared__ float red2[256];
    int row = blockIdx.x;
    const float* xr = x + (long long)row * C;
    float s = 0.f, sq = 0.f;
    for (int c = threadIdx.x; c < C; c += blockDim.x) {
        float v = xr[c];
        s += v; sq += v * v;
    }
    red[threadIdx.x] = s; red2[threadIdx.x] = sq;
    __syncthreads();
    for (int off = 128; off > 0; off >>= 1) {
        if (threadIdx.x < off) {
            red[threadIdx.x] += red[threadIdx.x + off];
            red2[threadIdx.x] += red2[threadIdx.x + off];
        }
        __syncthreads();
    }
    float mean = red[0] / C;
    float var = red2[0] / C - mean * mean;
    float rstd = rsqrtf(var + EPS);
    float* o = out + (long long)row * C;
    for (int c = threadIdx.x; c < C; c += blockDim.x)
        o[c] = (xr[c] - mean) * rstd * w[c] + b[c];
}

// ---------------- gelu ----------------
__device__ __forceinline__ float gelu_f(float x) {
    float x3 = x * x * x;
    return 0.5f * x * (1.f + tanhf(0.7978845608028654f * (x + 0.044715f * x3)));
}

__device__ __forceinline__ unsigned tf32_of(float f) {
    unsigned u;
    asm("cvt.rna.tf32.f32 %0, %1;" : "=r"(u) : "f"(f));
    return u;
}

// ---------------- tf32 tensor-core GEMM ----------------
// out[M,N] = A[M,K] @ W[K,N]; epi: 0=+bias, 1=gelu(+bias), 2=+bias+out(residual), 3=none
#define ASTR 20
#define BSTR 136

__global__ void __launch_bounds__(256)
tgemm_kernel(const float* __restrict__ A, const float* __restrict__ W,
             const float* __restrict__ bias, float* __restrict__ out,
             int M, int N, int K, int epi) {
    __shared__ unsigned As[2][128 * ASTR];
    __shared__ unsigned Bs[2][16 * BSTR];

    int tid = threadIdx.x;
    int warp = tid >> 5, lane = tid & 31;
    int g = lane >> 2, tig = lane & 3;
    int wm = (warp & 1) * 64;
    int wn = (warp >> 1) * 32;
    int m0 = blockIdx.y * 128;
    int n0 = blockIdx.x * 128;

    float c[4][4][4];
#pragma unroll
    for (int mi = 0; mi < 4; mi++)
#pragma unroll
        for (int nj = 0; nj < 4; nj++)
#pragma unroll
            for (int r = 0; r < 4; r++) c[mi][nj][r] = 0.f;

    int a_m = tid >> 2;
    int a_k = (tid & 3) * 4;
    int b_k = tid >> 5;
    int b_n = (tid & 31) * 4;

    float4 ra0, ra1;
    float rb[2][4];

    {
        ra0 = *(const float4*)(A + (long long)(m0 + a_m) * K + a_k);
        ra1 = *(const float4*)(A + (long long)(m0 + a_m + 64) * K + a_k);
#pragma unroll
        for (int i = 0; i < 2; i++) {
            const float* wr = W + (long long)(b_k + 8 * i) * N;
#pragma unroll
            for (int j = 0; j < 4; j++) {
                int col = n0 + b_n + j;
                rb[i][j] = (col < N) ? wr[col] : 0.f;
            }
        }
        unsigned* as = As[0];
        as[a_m * ASTR + a_k + 0] = tf32_of(ra0.x);
        as[a_m * ASTR + a_k + 1] = tf32_of(ra0.y);
        as[a_m * ASTR + a_k + 2] = tf32_of(ra0.z);
        as[a_m * ASTR + a_k + 3] = tf32_of(ra0.w);
        as[(a_m + 64) * ASTR + a_k + 0] = tf32_of(ra1.x);
        as[(a_m + 64) * ASTR + a_k + 1] = tf32_of(ra1.y);
        as[(a_m + 64) * ASTR + a_k + 2] = tf32_of(ra1.z);
        as[(a_m + 64) * ASTR + a_k + 3] = tf32_of(ra1.w);
        unsigned* bs = Bs[0];
#pragma unroll
        for (int i = 0; i < 2; i++)
#pragma unroll
            for (int j = 0; j < 4; j++)
                bs[(b_k + 8 * i) * BSTR + b_n + j] = tf32_of(rb[i][j]);
    }
    __syncthreads();

    int nk = K / 16;
    for (int kt = 0; kt < nk; kt++) {
        int cur = kt & 1, nxt = cur ^ 1;
        bool more = (kt + 1 < nk);
        if (more) {
            int k0 = (kt + 1) * 16;
            ra0 = *(const float4*)(A + (long long)(m0 + a_m) * K + k0 + a_k);
            ra1 = *(const float4*)(A + (long long)(m0 + a_m + 64) * K + k0 + a_k);
#pragma unroll
            for (int i = 0; i < 2; i++) {
                const float* wr = W + (long long)(k0 + b_k + 8 * i) * N;
#pragma unroll
                for (int j = 0; j < 4; j++) {
                    int col = n0 + b_n + j;
                    rb[i][j] = (col < N) ? wr[col] : 0.f;
                }
            }
        }

        const unsigned* as = As[cur];
        const unsigned* bs = Bs[cur];
#pragma unroll
        for (int kk = 0; kk < 2; kk++) {
            unsigned af[4][4], bf[4][2];
#pragma unroll
            for (int mi = 0; mi < 4; mi++) {
                int r = wm + mi * 16 + g;
                af[mi][0] = as[r * ASTR + kk * 8 + tig];
                af[mi][1] = as[(r + 8) * ASTR + kk * 8 + tig];
                af[mi][2] = as[r * ASTR + kk * 8 + tig + 4];
                af[mi][3] = as[(r + 8) * ASTR + kk * 8 + tig + 4];
            }
#pragma unroll
            for (int nj = 0; nj < 4; nj++) {
                int col = wn + nj * 8 + g;
                bf[nj][0] = bs[(kk * 8 + tig) * BSTR + col];
                bf[nj][1] = bs[(kk * 8 + tig + 4) * BSTR + col];
            }
#pragma unroll
            for (int mi = 0; mi < 4; mi++)
#pragma unroll
                for (int nj = 0; nj < 4; nj++)
                    asm volatile(
                        "mma.sync.aligned.m16n8k8.row.col.f32.tf32.tf32.f32 "
                        "{%0,%1,%2,%3},{%4,%5,%6,%7},{%8,%9},{%0,%1,%2,%3};\n"
                        : "+f"(c[mi][nj][0]), "+f"(c[mi][nj][1]),
                          "+f"(c[mi][nj][2]), "+f"(c[mi][nj][3])
                        : "r"(af[mi][0]), "r"(af[mi][1]), "r"(af[mi][2]), "r"(af[mi][3]),
                          "r"(bf[nj][0]), "r"(bf[nj][1]));
        }

        if (more) {
            unsigned* asn = As[nxt];
            asn[a_m * ASTR + a_k + 0] = tf32_of(ra0.x);
            asn[a_m * ASTR + a_k + 1] = tf32_of(ra0.y);
            asn[a_m * ASTR + a_k + 2] = tf32_of(ra0.z);
            asn[a_m * ASTR + a_k + 3] = tf32_of(ra0.w);
            asn[(a_m + 64) * ASTR + a_k + 0] = tf32_of(ra1.x);
            asn[(a_m + 64) * ASTR + a_k + 1] = tf32_of(ra1.y);
            asn[(a_m + 64) * ASTR + a_k + 2] = tf32_of(ra1.z);
            asn[(a_m + 64) * ASTR + a_k + 3] = tf32_of(ra1.w);
            unsigned* bsn = Bs[nxt];
#pragma unroll
            for (int i = 0; i < 2; i++)
#pragma unroll
                for (int j = 0; j < 4; j++)
                    bsn[(b_k + 8 * i) * BSTR + b_n + j] = tf32_of(rb[i][j]);
        }
        __syncthreads();
    }

#pragma unroll
    for (int mi = 0; mi < 4; mi++) {
        int r0 = m0 + wm + mi * 16 + g;
#pragma unroll
        for (int nj = 0; nj < 4; nj++) {
            int col = n0 + wn + nj * 8 + 2 * tig;
#pragma unroll
            for (int half = 0; half < 2; half++) {
                int rr = r0 + half * 8;
#pragma unroll
                for (int jj = 0; jj < 2; jj++) {
                    int cc = col + jj;
                    if (cc < N) {
                        float v = c[mi][nj][half * 2 + jj];
                        if (epi != 3) v += bias[cc];
                        if (epi == 1) v = gelu_f(v);
                        long long o = (long long)rr * N + cc;
                        if (epi == 2) v += out[o];
                        out[o] = v;
                    }
                }
            }
        }
    }
}

// ---------------- tiled fp32 flash attention ----------------
// Block: 64 queries x 1 head. KV tiles of 32. 256 threads as 16(ty: 4 q-rows) x 16(tx).
// Phase A: scores s[4][2] per thread (cols tx*2). Online softmax via 16-lane shfl.
// P routed through smem. Phase B: O[4][4] per thread (HD cols tx*4).
__global__ void __launch_bounds__(256)
fattn_kernel(const float* __restrict__ qkv, float* __restrict__ out) {
    __shared__ float sQt[64][68];   // [d][q]
    __shared__ float sKt[64][36];   // [d][kv]
    __shared__ float sV[32][68];    // [kv][d]
    __shared__ float sP[64][36];    // [q][kv]

    int tid = threadIdx.x;
    int tx = tid & 15, ty = tid >> 4;
    int qt = (int)gridDim.x - 1 - (int)blockIdx.x;  // heavy tiles first
    int h = blockIdx.y, b = blockIdx.z;
    int q0 = qt * 64;

    // load Q tile transposed (once)
    {
        int r = tid >> 4;        // 0..15
        int c4 = (tid & 15) * 4; // 0..60
#pragma unroll
        for (int rr = 0; rr < 64; rr += 16) {
            const float* qrow = qkv + (long long)(b * Tlen + q0 + r + rr) * C3 + h * HD;
            float4 v = *(const float4*)(qrow + c4);
            sQt[c4 + 0][r + rr] = v.x;
            sQt[c4 + 1][r + rr] = v.y;
            sQt[c4 + 2][r + rr] = v.z;
            sQt[c4 + 3][r + rr] = v.w;
        }
    }

    float O[4][4] = {};
    float m[4], l[4];
#pragma unroll
    for (int i = 0; i < 4; i++) { m[i] = -INFINITY; l[i] = 0.f; }

    const float scale = 0.125f;   // 1/sqrt(64)
    int ntiles = 2 * qt + 2;

    for (int kt = 0; kt < ntiles; kt++) {
        int kv0 = kt * 32;
        __syncthreads();
        // load K (transposed) + V tile
        {
            int r = tid >> 4;
            int c4 = (tid & 15) * 4;
#pragma unroll
            for (int half = 0; half < 2; half++) {
                int rr = r + half * 16;
                const float* krow = qkv + (long long)(b * Tlen + kv0 + rr) * C3 + C + h * HD;
                float4 kv4 = *(const float4*)(krow + c4);
                sKt[c4 + 0][rr] = kv4.x;
                sKt[c4 + 1][rr] = kv4.y;
                sKt[c4 + 2][rr] = kv4.z;
                sKt[c4 + 3][rr] = kv4.w;
                const float* vrow = qkv + (long long)(b * Tlen + kv0 + rr) * C3 + 2 * C + h * HD;
                *(float4*)&sV[rr][c4] = *(const float4*)(vrow + c4);
            }
        }
        __syncthreads();

        // phase A: scores
        float s[4][2] = {};
#pragma unroll 16
        for (int kk = 0; kk < 64; kk++) {
            float4 a = *(const float4*)&sQt[kk][ty * 4];
            float2 bv = *(const float2*)&sKt[kk][tx * 2];
            s[0][0] += a.x * bv.x; s[0][1] += a.x * bv.y;
            s[1][0] += a.y * bv.x; s[1][1] += a.y * bv.y;
            s[2][0] += a.z * bv.x; s[2][1] += a.z * bv.y;
            s[3][0] += a.w * bv.x; s[3][1] += a.w * bv.y;
        }
#pragma unroll
        for (int i = 0; i < 4; i++) {
            s[i][0] *= scale; s[i][1] *= scale;
        }
        if (kt >= 2 * qt) {   // diagonal tiles: causal mask
#pragma unroll
            for (int i = 0; i < 4; i++) {
                int qg = q0 + ty * 4 + i;
#pragma unroll
                for (int j = 0; j < 2; j++) {
                    if (kv0 + tx * 2 + j > qg) s[i][j] = -INFINITY;
                }
            }
        }

        // online softmax (per row; 16-lane reduction)
#pragma unroll
        for (int i = 0; i < 4; i++) {
            float rm = fmaxf(s[i][0], s[i][1]);
#pragma unroll
            for (int off = 1; off < 16; off <<= 1)
                rm = fmaxf(rm, __shfl_xor_sync(0xFFFFFFFFu, rm, off));
            float mn = fmaxf(m[i], rm);
            float cs = __expf(m[i] - mn);
            float p0 = __expf(s[i][0] - mn);
            float p1 = __expf(s[i][1] - mn);
            float rs = p0 + p1;
#pragma unroll
            for (int off = 1; off < 16; off <<= 1)
                rs += __shfl_xor_sync(0xFFFFFFFFu, rs, off);
            l[i] = l[i] * cs + rs;
            m[i] = mn;
            O[i][0] *= cs; O[i][1] *= cs; O[i][2] *= cs; O[i][3] *= cs;
            sP[ty * 4 + i][tx * 2 + 0] = p0;
            sP[ty * 4 + i][tx * 2 + 1] = p1;
        }
        __syncthreads();

        // phase B: O += P @ V
#pragma unroll 8
        for (int kv = 0; kv < 32; kv++) {
            float4 v = *(const float4*)&sV[kv][tx * 4];
            float p0 = sP[ty * 4 + 0][kv];
            float p1 = sP[ty * 4 + 1][kv];
            float p2 = sP[ty * 4 + 2][kv];
            float p3 = sP[ty * 4 + 3][kv];
            O[0][0] += p0 * v.x; O[0][1] += p0 * v.y; O[0][2] += p0 * v.z; O[0][3] += p0 * v.w;
            O[1][0] += p1 * v.x; O[1][1] += p1 * v.y; O[1][2] += p1 * v.z; O[1][3] += p1 * v.w;
            O[2][0] += p2 * v.x; O[2][1] += p2 * v.y; O[2][2] += p2 * v.z; O[2][3] += p2 * v.w;
            O[3][0] += p3 * v.x; O[3][1] += p3 * v.y; O[3][2] += p3 * v.z; O[3][3] += p3 * v.w;
        }
    }

    // write O / l
#pragma unroll
    for (int i = 0; i < 4; i++) {
        float inv = 1.f / l[i];
        float4 o4;
        o4.x = O[i][0] * inv; o4.y = O[i][1] * inv;
        o4.z = O[i][2] * inv; o4.w = O[i][3] * inv;
        float* o = out + (long long)(b * Tlen + q0 + ty * 4 + i) * C + h * HD + tx * 4;
        *(float4*)o = o4;
    }
}

// ---------------- driver ----------------
extern "C" void kernel_launch(void* const* d_in, const int* in_sizes, int n_in,
                              void* d_out, int out_size) {
    const int*   idx      = (const int*)  d_in[0];
    const float* wte      = (const float*)d_in[1];
    const float* wpe      = (const float*)d_in[2];
    const float* ln1_w    = (const float*)d_in[3];
    const float* ln1_b    = (const float*)d_in[4];
    const float* attn_w   = (const float*)d_in[5];
    const float* attn_b   = (const float*)d_in[6];
    const float* proj_w   = (const float*)d_in[7];
    const float* proj_b   = (const float*)d_in[8];
    const float* ln2_w    = (const float*)d_in[9];
    const float* ln2_b    = (const float*)d_in[10];
    const float* fc_w     = (const float*)d_in[11];
    const float* fc_b     = (const float*)d_in[12];
    const float* fcproj_w = (const float*)d_in[13];
    const float* fcproj_b = (const float*)d_in[14];
    const float* lnf_w    = (const float*)d_in[15];
    const float* lnf_b    = (const float*)d_in[16];
    const float* lm_head  = (const float*)d_in[17];
    float* out = (float*)d_out;

    float *x, *ln, *qkv, *atty, *hbuf;
    cudaGetSymbolAddress((void**)&x,    g_x);
    cudaGetSymbolAddress((void**)&ln,   g_ln);
    cudaGetSymbolAddress((void**)&qkv,  g_qkv);
    cudaGetSymbolAddress((void**)&atty, g_atty);
    cudaGetSymbolAddress((void**)&hbuf, g_h);

    embed_kernel<<<BT, 256>>>(idx, wte, wpe, x);

    for (int l = 0; l < NL; l++) {
        ln_kernel<<<BT, 256>>>(x, ln1_w + l * C, ln1_b + l * C, ln);
        tgemm_kernel<<<dim3(C3 / 128, BT / 128), 256>>>(
            ln, attn_w + (long long)l * C * C3, attn_b + l * C3, qkv, BT, C3, C, 0);
        fattn_kernel<<<dim3(Tlen / 64, H, Bsz), 256>>>(qkv, atty);
        tgemm_kernel<<<dim3(C / 128, BT / 128), 256>>>(
            atty, proj_w + (long long)l * C * C, proj_b + l * C, x, BT, C, C, 2);
        ln_kernel<<<BT, 256>>>(x, ln2_w + l * C, ln2_b + l * C, ln);
        tgemm_kernel<<<dim3(C4 / 128, BT / 128), 256>>>(
            ln, fc_w + (long long)l * C * C4, fc_b + l * C4, hbuf, BT, C4, C, 1);
        tgemm_kernel<<<dim3(C / 128, BT / 128), 256>>>(
            hbuf, fcproj_w + (long long)l * C4 * C, fcproj_b + l * C, x, BT, C, C4, 2);
    }

    ln_kernel<<<BT, 256>>>(x, lnf_w, lnf_b, ln);
    tgemm_kernel<<<dim3((V + 127) / 128, BT / 128), 256>>>(
        ln, lm_head, (const float*)nullptr, out, BT, V, C, 3);
}

// round 4
// speedup vs baseline: 3.9710x; 1.1512x over previous
#include <cuda_runtime.h>
#include <math.h>

// GPT-2 small forward: cp.async-pipelined tf32 tensor GEMMs + tiled fp32 flash attention.
// B=2, T=1024, C=768, H=12, HD=64, L=12, V=50257.

#define Bsz 2
#define Tlen 1024
#define BT (Bsz * Tlen)      // 2048
#define C 768
#define H 12
#define HD 64
#define NL 12
#define V 50257
#define C3 (3 * C)           // 2304
#define C4 (4 * C)           // 3072
#define EPS 1e-5f

// ---------------- scratch ----------------
__device__ float g_x[BT * C];
__device__ float g_ln[BT * C];
__device__ float g_qkv[BT * C3];
__device__ float g_atty[BT * C];
__device__ float g_h[BT * C4];

// ---------------- embedding ----------------
__global__ void embed_kernel(const int* __restrict__ idx,
                             const float* __restrict__ wte,
                             const float* __restrict__ wpe,
                             float* __restrict__ out) {
    int row = blockIdx.x;
    int tpos = row % Tlen;
    int tok = idx[row];
    const float* we = wte + (long long)tok * C;
    const float* pe = wpe + (long long)tpos * C;
    float* o = out + (long long)row * C;
    for (int c = threadIdx.x; c < C; c += blockDim.x)
        o[c] = we[c] + pe[c];
}

// ---------------- layernorm ----------------
__global__ void ln_kernel(const float* __restrict__ x,
                          const float* __restrict__ w,
                          const float* __restrict__ b,
                          float* __restrict__ out) {
    __shared__ float red[256];
    __shared__ float red2[256];
    int row = blockIdx.x;
    const float* xr = x + (long long)row * C;
    float s = 0.f, sq = 0.f;
    for (int c = threadIdx.x; c < C; c += blockDim.x) {
        float v = xr[c];
        s += v; sq += v * v;
    }
    red[threadIdx.x] = s; red2[threadIdx.x] = sq;
    __syncthreads();
    for (int off = 128; off > 0; off >>= 1) {
        if (threadIdx.x < off) {
            red[threadIdx.x] += red[threadIdx.x + off];
            red2[threadIdx.x] += red2[threadIdx.x + off];
        }
        __syncthreads();
    }
    float mean = red[0] / C;
    float var = red2[0] / C - mean * mean;
    float rstd = rsqrtf(var + EPS);
    float* o = out + (long long)row * C;
    for (int c = threadIdx.x; c < C; c += blockDim.x)
        o[c] = (xr[c] - mean) * rstd * w[c] + b[c];
}

// ---------------- helpers ----------------
__device__ __forceinline__ float gelu_f(float x) {
    float x3 = x * x * x;
    return 0.5f * x * (1.f + tanhf(0.7978845608028654f * (x + 0.044715f * x3)));
}

__device__ __forceinline__ unsigned tf32_of(float f) {
    unsigned u;
    asm("cvt.rna.tf32.f32 %0, %1;" : "=r"(u) : "f"(f));
    return u;
}

__device__ __forceinline__ unsigned sptr(const void* p) {
    return (unsigned)__cvta_generic_to_shared(p);
}

// ---------------- cp.async double-buffered tf32 GEMM ----------------
// out[M,N] = A[M,K] @ W[K,N]; epi: 0=+bias, 1=gelu(+bias), 2=+bias+residual, 3=none
// Block: 128 threads (4 warps, 2x2), tile BM x 128, warp tile (BM/2) x 64, K-tile 16.
// smem holds raw fp32 (filled by LDGSTS); tf32 conversion at fragment load (idle ALU pipe).
#define ASTR 20      // 16 + 4 pad (floats)
#define BSTR 136     // 128 + 8 pad (floats)

template<int BM, bool AL>
__global__ void __launch_bounds__(128)
tgemm_kernel(const float* __restrict__ A, const float* __restrict__ W,
             const float* __restrict__ bias, float* __restrict__ out,
             int M, int N, int K, int epi) {
    constexpr int MI = BM / 32;           // m-fragments per warp (16-row steps over BM/2 rows)
    __shared__ float As[2][BM * ASTR];
    __shared__ float Bs[2][16 * BSTR];

    int tid = threadIdx.x;
    int w = tid >> 5, lane = tid & 31;
    int g = lane >> 2, tig = lane & 3;
    int wm = (w & 1) * (BM / 2);
    int wn = (w >> 1) * 64;
    int m0 = blockIdx.y * BM;
    int n0 = blockIdx.x * 128;

    float acc[MI][8][4];
#pragma unroll
    for (int mi = 0; mi < MI; mi++)
#pragma unroll
        for (int nj = 0; nj < 8; nj++)
#pragma unroll
            for (int r = 0; r < 4; r++) acc[mi][nj][r] = 0.f;

    auto loadTiles = [&](int kt, int s) {
        int k0 = kt * 16;
        // A tile: BM rows x 16 k, 16B chunks
#pragma unroll
        for (int i = 0; i < BM / 32; i++) {
            int id = tid + i * 128;
            int row = id >> 2, kc = (id & 3) * 4;
            unsigned dst = sptr(&As[s][row * ASTR + kc]);
            const float* src = A + (long long)(m0 + row) * K + k0 + kc;
            asm volatile("cp.async.cg.shared.global [%0], [%1], 16;" :: "r"(dst), "l"(src));
        }
        if (AL) {
            // B tile: 16 rows x 128 cols, 16B chunks (N multiple of 128, rows 16B-aligned)
#pragma unroll
            for (int i = 0; i < 4; i++) {
                int id = tid + i * 128;
                int row = id >> 5, nc = (id & 31) * 4;
                unsigned dst = sptr(&Bs[s][row * BSTR + nc]);
                const float* src = W + (long long)(k0 + row) * N + n0 + nc;
                asm volatile("cp.async.cg.shared.global [%0], [%1], 16;" :: "r"(dst), "l"(src));
            }
        } else {
            // unaligned / ragged N: 4B chunks with zero-fill at the edge
#pragma unroll
            for (int i = 0; i < 16; i++) {
                int id = tid + i * 128;
                int row = id >> 7, ncol = id & 127;
                unsigned dst = sptr(&Bs[s][row * BSTR + ncol]);
                const float* src = W + (long long)(k0 + row) * N + n0 + ncol;
                int nb = (n0 + ncol < N) ? 4 : 0;
                asm volatile("cp.async.ca.shared.global [%0], [%1], 4, %2;"
                             :: "r"(dst), "l"(src), "r"(nb));
            }
        }
    };

    int nk = K / 16;
    loadTiles(0, 0);
    asm volatile("cp.async.commit_group;");

    for (int kt = 0; kt < nk; kt++) {
        int cur = kt & 1, nxt = cur ^ 1;
        if (kt + 1 < nk) loadTiles(kt + 1, nxt);
        asm volatile("cp.async.commit_group;");
        asm volatile("cp.async.wait_group 1;");
        __syncthreads();

        const float* as = As[cur];
        const float* bs = Bs[cur];
#pragma unroll
        for (int kk = 0; kk < 2; kk++) {
            unsigned af[MI][4], bf[8][2];
#pragma unroll
            for (int mi = 0; mi < MI; mi++) {
                int r = wm + mi * 16 + g;
                af[mi][0] = tf32_of(as[r * ASTR + kk * 8 + tig]);
                af[mi][1] = tf32_of(as[(r + 8) * ASTR + kk * 8 + tig]);
                af[mi][2] = tf32_of(as[r * ASTR + kk * 8 + tig + 4]);
                af[mi][3] = tf32_of(as[(r + 8) * ASTR + kk * 8 + tig + 4]);
            }
#pragma unroll
            for (int nj = 0; nj < 8; nj++) {
                int col = wn + nj * 8 + g;
                bf[nj][0] = tf32_of(bs[(kk * 8 + tig) * BSTR + col]);
                bf[nj][1] = tf32_of(bs[(kk * 8 + tig + 4) * BSTR + col]);
            }
#pragma unroll
            for (int mi = 0; mi < MI; mi++)
#pragma unroll
                for (int nj = 0; nj < 8; nj++)
                    asm volatile(
                        "mma.sync.aligned.m16n8k8.row.col.f32.tf32.tf32.f32 "
                        "{%0,%1,%2,%3},{%4,%5,%6,%7},{%8,%9},{%0,%1,%2,%3};\n"
                        : "+f"(acc[mi][nj][0]), "+f"(acc[mi][nj][1]),
                          "+f"(acc[mi][nj][2]), "+f"(acc[mi][nj][3])
                        : "r"(af[mi][0]), "r"(af[mi][1]), "r"(af[mi][2]), "r"(af[mi][3]),
                          "r"(bf[nj][0]), "r"(bf[nj][1]));
        }
        __syncthreads();
    }

    // ---- epilogue ----
#pragma unroll
    for (int mi = 0; mi < MI; mi++) {
        int r0 = m0 + wm + mi * 16 + g;
#pragma unroll
        for (int nj = 0; nj < 8; nj++) {
            int col = n0 + wn + nj * 8 + 2 * tig;
#pragma unroll
            for (int half = 0; half < 2; half++) {
                int rr = r0 + half * 8;
#pragma unroll
                for (int jj = 0; jj < 2; jj++) {
                    int cc = col + jj;
                    if (cc < N) {
                        float v = acc[mi][nj][half * 2 + jj];
                        if (epi != 3) v += bias[cc];
                        if (epi == 1) v = gelu_f(v);
                        long long o = (long long)rr * N + cc;
                        if (epi == 2) v += out[o];
                        out[o] = v;
                    }
                }
            }
        }
    }
}

// ---------------- tiled fp32 flash attention ----------------
__global__ void __launch_bounds__(256)
fattn_kernel(const float* __restrict__ qkv, float* __restrict__ out) {
    __shared__ float sQt[64][68];   // [d][q]
    __shared__ float sKt[64][36];   // [d][kv]
    __shared__ float sV[32][68];    // [kv][d]
    __shared__ float sP[64][36];    // [q][kv]

    int tid = threadIdx.x;
    int tx = tid & 15, ty = tid >> 4;
    int qt = (int)gridDim.x - 1 - (int)blockIdx.x;  // heavy tiles first
    int h = blockIdx.y, b = blockIdx.z;
    int q0 = qt * 64;

    {
        int r = tid >> 4;
        int c4 = (tid & 15) * 4;
#pragma unroll
        for (int rr = 0; rr < 64; rr += 16) {
            const float* qrow = qkv + (long long)(b * Tlen + q0 + r + rr) * C3 + h * HD;
            float4 v = *(const float4*)(qrow + c4);
            sQt[c4 + 0][r + rr] = v.x;
            sQt[c4 + 1][r + rr] = v.y;
            sQt[c4 + 2][r + rr] = v.z;
            sQt[c4 + 3][r + rr] = v.w;
        }
    }

    float O[4][4] = {};
    float m[4], l[4];
#pragma unroll
    for (int i = 0; i < 4; i++) { m[i] = -INFINITY; l[i] = 0.f; }

    const float scale = 0.125f;
    int ntiles = 2 * qt + 2;

    for (int kt = 0; kt < ntiles; kt++) {
        int kv0 = kt * 32;
        __syncthreads();
        {
            int r = tid >> 4;
            int c4 = (tid & 15) * 4;
#pragma unroll
            for (int half = 0; half < 2; half++) {
                int rr = r + half * 16;
                const float* krow = qkv + (long long)(b * Tlen + kv0 + rr) * C3 + C + h * HD;
                float4 kv4 = *(const float4*)(krow + c4);
                sKt[c4 + 0][rr] = kv4.x;
                sKt[c4 + 1][rr] = kv4.y;
                sKt[c4 + 2][rr] = kv4.z;
                sKt[c4 + 3][rr] = kv4.w;
                const float* vrow = qkv + (long long)(b * Tlen + kv0 + rr) * C3 + 2 * C + h * HD;
                *(float4*)&sV[rr][c4] = *(const float4*)(vrow + c4);
            }
        }
        __syncthreads();

        float s[4][2] = {};
#pragma unroll 16
        for (int kk = 0; kk < 64; kk++) {
            float4 a = *(const float4*)&sQt[kk][ty * 4];
            float2 bv = *(const float2*)&sKt[kk][tx * 2];
            s[0][0] += a.x * bv.x; s[0][1] += a.x * bv.y;
            s[1][0] += a.y * bv.x; s[1][1] += a.y * bv.y;
            s[2][0] += a.z * bv.x; s[2][1] += a.z * bv.y;
            s[3][0] += a.w * bv.x; s[3][1] += a.w * bv.y;
        }
#pragma unroll
        for (int i = 0; i < 4; i++) { s[i][0] *= scale; s[i][1] *= scale; }
        if (kt >= 2 * qt) {
#pragma unroll
            for (int i = 0; i < 4; i++) {
                int qg = q0 + ty * 4 + i;
#pragma unroll
                for (int j = 0; j < 2; j++)
                    if (kv0 + tx * 2 + j > qg) s[i][j] = -INFINITY;
            }
        }

#pragma unroll
        for (int i = 0; i < 4; i++) {
            float rm = fmaxf(s[i][0], s[i][1]);
#pragma unroll
            for (int off = 1; off < 16; off <<= 1)
                rm = fmaxf(rm, __shfl_xor_sync(0xFFFFFFFFu, rm, off));
            float mn = fmaxf(m[i], rm);
            float cs = __expf(m[i] - mn);
            float p0 = __expf(s[i][0] - mn);
            float p1 = __expf(s[i][1] - mn);
            float rs = p0 + p1;
#pragma unroll
            for (int off = 1; off < 16; off <<= 1)
                rs += __shfl_xor_sync(0xFFFFFFFFu, rs, off);
            l[i] = l[i] * cs + rs;
            m[i] = mn;
            O[i][0] *= cs; O[i][1] *= cs; O[i][2] *= cs; O[i][3] *= cs;
            sP[ty * 4 + i][tx * 2 + 0] = p0;
            sP[ty * 4 + i][tx * 2 + 1] = p1;
        }
        __syncthreads();

#pragma unroll 8
        for (int kv = 0; kv < 32; kv++) {
            float4 v = *(const float4*)&sV[kv][tx * 4];
            float p0 = sP[ty * 4 + 0][kv];
            float p1 = sP[ty * 4 + 1][kv];
            float p2 = sP[ty * 4 + 2][kv];
            float p3 = sP[ty * 4 + 3][kv];
            O[0][0] += p0 * v.x; O[0][1] += p0 * v.y; O[0][2] += p0 * v.z; O[0][3] += p0 * v.w;
            O[1][0] += p1 * v.x; O[1][1] += p1 * v.y; O[1][2] += p1 * v.z; O[1][3] += p1 * v.w;
            O[2][0] += p2 * v.x; O[2][1] += p2 * v.y; O[2][2] += p2 * v.z; O[2][3] += p2 * v.w;
            O[3][0] += p3 * v.x; O[3][1] += p3 * v.y; O[3][2] += p3 * v.z; O[3][3] += p3 * v.w;
        }
    }

#pragma unroll
    for (int i = 0; i < 4; i++) {
        float inv = 1.f / l[i];
        float4 o4;
        o4.x = O[i][0] * inv; o4.y = O[i][1] * inv;
        o4.z = O[i][2] * inv; o4.w = O[i][3] * inv;
        float* o = out + (long long)(b * Tlen + q0 + ty * 4 + i) * C + h * HD + tx * 4;
        *(float4*)o = o4;
    }
}

// ---------------- driver ----------------
extern "C" void kernel_launch(void* const* d_in, const int* in_sizes, int n_in,
                              void* d_out, int out_size) {
    const int*   idx      = (const int*)  d_in[0];
    const float* wte      = (const float*)d_in[1];
    const float* wpe      = (const float*)d_in[2];
    const float* ln1_w    = (const float*)d_in[3];
    const float* ln1_b    = (const float*)d_in[4];
    const float* attn_w   = (const float*)d_in[5];
    const float* attn_b   = (const float*)d_in[6];
    const float* proj_w   = (const float*)d_in[7];
    const float* proj_b   = (const float*)d_in[8];
    const float* ln2_w    = (const float*)d_in[9];
    const float* ln2_b    = (const float*)d_in[10];
    const float* fc_w     = (const float*)d_in[11];
    const float* fc_b     = (const float*)d_in[12];
    const float* fcproj_w = (const float*)d_in[13];
    const float* fcproj_b = (const float*)d_in[14];
    const float* lnf_w    = (const float*)d_in[15];
    const float* lnf_b    = (const float*)d_in[16];
    const float* lm_head  = (const float*)d_in[17];
    float* out = (float*)d_out;

    float *x, *ln, *qkv, *atty, *hbuf;
    cudaGetSymbolAddress((void**)&x,    g_x);
    cudaGetSymbolAddress((void**)&ln,   g_ln);
    cudaGetSymbolAddress((void**)&qkv,  g_qkv);
    cudaGetSymbolAddress((void**)&atty, g_atty);
    cudaGetSymbolAddress((void**)&hbuf, g_h);

    embed_kernel<<<BT, 256>>>(idx, wte, wpe, x);

    for (int l = 0; l < NL; l++) {
        ln_kernel<<<BT, 256>>>(x, ln1_w + l * C, ln1_b + l * C, ln);
        tgemm_kernel<128, true><<<dim3(C3 / 128, BT / 128), 128>>>(
            ln, attn_w + (long long)l * C * C3, attn_b + l * C3, qkv, BT, C3, C, 0);
        fattn_kernel<<<dim3(Tlen / 64, H, Bsz), 256>>>(qkv, atty);
        tgemm_kernel<64, true><<<dim3(C / 128, BT / 64), 128>>>(
            atty, proj_w + (long long)l * C * C, proj_b + l * C, x, BT, C, C, 2);
        ln_kernel<<<BT, 256>>>(x, ln2_w + l * C, ln2_b + l * C, ln);
        tgemm_kernel<128, true><<<dim3(C4 / 128, BT / 128), 128>>>(
            ln, fc_w + (long long)l * C * C4, fc_b + l * C4, hbuf, BT, C4, C, 1);
        tgemm_kernel<64, true><<<dim3(C / 128, BT / 64), 128>>>(
            hbuf, fcproj_w + (long long)l * C4 * C, fcproj_b + l * C, x, BT, C, C4, 2);
    }

    ln_kernel<<<BT, 256>>>(x, lnf_w, lnf_b, ln);
    tgemm_kernel<128, false><<<dim3((V + 127) / 128, BT / 128), 128>>>(
        ln, lm_head, (const float*)nullptr, out, BT, V, C, 3);
}

// round 5
// speedup vs baseline: 3.9816x; 1.0027x over previous
#include <cuda_runtime.h>
#include <math.h>

// GPT-2 small forward: 3-stage cp.async tf32 tensor GEMMs + tiled fp32 flash attention.
// B=2, T=1024, C=768, H=12, HD=64, L=12, V=50257.

#define Bsz 2
#define Tlen 1024
#define BT (Bsz * Tlen)      // 2048
#define C 768
#define H 12
#define HD 64
#define NL 12
#define V 50257
#define VP 50304             // V padded to multiple of 128 (16B-aligned rows)
#define C3 (3 * C)           // 2304
#define C4 (4 * C)           // 3072
#define EPS 1e-5f

// ---------------- scratch ----------------
__device__ float g_x[BT * C];
__device__ float g_ln[BT * C];
__device__ float g_qkv[BT * C3];
__device__ float g_atty[BT * C];
__device__ float g_h[BT * C4];
__device__ float g_wpad[(long long)C * VP];   // padded lm_head weights

// ---------------- embedding ----------------
__global__ void embed_kernel(const int* __restrict__ idx,
                             const float* __restrict__ wte,
                             const float* __restrict__ wpe,
                             float* __restrict__ out) {
    int row = blockIdx.x;
    int tpos = row % Tlen;
    int tok = idx[row];
    const float* we = wte + (long long)tok * C;
    const float* pe = wpe + (long long)tpos * C;
    float* o = out + (long long)row * C;
    for (int c = threadIdx.x; c < C; c += blockDim.x)
        o[c] = we[c] + pe[c];
}

// ---------------- lm_head weight padding ----------------
__global__ void padw_kernel(const float* __restrict__ w, float* __restrict__ wp) {
    int k = blockIdx.y;
    int n = blockIdx.x * blockDim.x + threadIdx.x;
    if (n < VP)
        wp[(long long)k * VP + n] = (n < V) ? w[(long long)k * V + n] : 0.f;
}

// ---------------- layernorm ----------------
__global__ void ln_kernel(const float* __restrict__ x,
                          const float* __restrict__ w,
                          const float* __restrict__ b,
                          float* __restrict__ out) {
    __shared__ float red[256];
    __shared__ float red2[256];
    int row = blockIdx.x;
    const float* xr = x + (long long)row * C;
    float s = 0.f, sq = 0.f;
    for (int c = threadIdx.x; c < C; c += blockDim.x) {
        float v = xr[c];
        s += v; sq += v * v;
    }
    red[threadIdx.x] = s; red2[threadIdx.x] = sq;
    __syncthreads();
    for (int off = 128; off > 0; off >>= 1) {
        if (threadIdx.x < off) {
            red[threadIdx.x] += red[threadIdx.x + off];
            red2[threadIdx.x] += red2[threadIdx.x + off];
        }
        __syncthreads();
    }
    float mean = red[0] / C;
    float var = red2[0] / C - mean * mean;
    float rstd = rsqrtf(var + EPS);
    float* o = out + (long long)row * C;
    for (int c = threadIdx.x; c < C; c += blockDim.x)
        o[c] = (xr[c] - mean) * rstd * w[c] + b[c];
}

// ---------------- helpers ----------------
__device__ __forceinline__ float gelu_f(float x) {
    float x3 = x * x * x;
    return 0.5f * x * (1.f + tanhf(0.7978845608028654f * (x + 0.044715f * x3)));
}

__device__ __forceinline__ unsigned tf32_of(float f) {
    unsigned u;
    asm("cvt.rna.tf32.f32 %0, %1;" : "=r"(u) : "f"(f));
    return u;
}

__device__ __forceinline__ unsigned sptr(const void* p) {
    return (unsigned)__cvta_generic_to_shared(p);
}

// ---------------- 3-stage cp.async tf32 GEMM ----------------
// out[M,N] = A[M,K] @ W[K,N] (W row stride ldw); epi: 0=+bias, 1=gelu, 2=+residual, 3=none
// 128 threads (4 warps 2x2), tile BM x 128, warp tile (BM/2) x 64, K-tile 16, 3 stages.
#define ASTR 20      // 16 + 4 pad
#define BSTR 136     // 128 + 8 pad

template<int BM>
__global__ void __launch_bounds__(128)
tgemm_kernel(const float* __restrict__ A, const float* __restrict__ W,
             const float* __restrict__ bias, float* __restrict__ out,
             int M, int N, int K, int ldw, int epi) {
    constexpr int MI = BM / 32;
    extern __shared__ float sm[];
    float* As = sm;                       // 3 stages of BM*ASTR
    float* Bs = sm + 3 * BM * ASTR;       // 3 stages of 16*BSTR

    int tid = threadIdx.x;
    int w = tid >> 5, lane = tid & 31;
    int g = lane >> 2, tig = lane & 3;
    int wm = (w & 1) * (BM / 2);
    int wn = (w >> 1) * 64;
    int m0 = blockIdx.y * BM;
    int n0 = blockIdx.x * 128;

    float acc[MI][8][4];
#pragma unroll
    for (int mi = 0; mi < MI; mi++)
#pragma unroll
        for (int nj = 0; nj < 8; nj++)
#pragma unroll
            for (int r = 0; r < 4; r++) acc[mi][nj][r] = 0.f;

    auto loadTiles = [&](int kt, int s) {
        int k0 = kt * 16;
        float* as = As + s * (BM * ASTR);
        float* bs = Bs + s * (16 * BSTR);
#pragma unroll
        for (int i = 0; i < BM / 32; i++) {
            int id = tid + i * 128;
            int row = id >> 2, kc = (id & 3) * 4;
            unsigned dst = sptr(&as[row * ASTR + kc]);
            const float* src = A + (long long)(m0 + row) * K + k0 + kc;
            asm volatile("cp.async.cg.shared.global [%0], [%1], 16;" :: "r"(dst), "l"(src));
        }
#pragma unroll
        for (int i = 0; i < 4; i++) {
            int id = tid + i * 128;
            int row = id >> 5, nc = (id & 31) * 4;
            unsigned dst = sptr(&bs[row * BSTR + nc]);
            const float* src = W + (long long)(k0 + row) * ldw + n0 + nc;
            asm volatile("cp.async.cg.shared.global [%0], [%1], 16;" :: "r"(dst), "l"(src));
        }
    };

    int nk = K / 16;
    loadTiles(0, 0);
    asm volatile("cp.async.commit_group;");
    loadTiles(1, 1);
    asm volatile("cp.async.commit_group;");

    for (int kt = 0; kt < nk; kt++) {
        asm volatile("cp.async.wait_group 1;");
        __syncthreads();

        int cur = kt % 3;
        const float* as = As + cur * (BM * ASTR);
        const float* bs = Bs + cur * (16 * BSTR);
#pragma unroll
        for (int kk = 0; kk < 2; kk++) {
            unsigned af[MI][4], bf[8][2];
#pragma unroll
            for (int mi = 0; mi < MI; mi++) {
                int r = wm + mi * 16 + g;
                af[mi][0] = tf32_of(as[r * ASTR + kk * 8 + tig]);
                af[mi][1] = tf32_of(as[(r + 8) * ASTR + kk * 8 + tig]);
                af[mi][2] = tf32_of(as[r * ASTR + kk * 8 + tig + 4]);
                af[mi][3] = tf32_of(as[(r + 8) * ASTR + kk * 8 + tig + 4]);
            }
#pragma unroll
            for (int nj = 0; nj < 8; nj++) {
                int col = wn + nj * 8 + g;
                bf[nj][0] = tf32_of(bs[(kk * 8 + tig) * BSTR + col]);
                bf[nj][1] = tf32_of(bs[(kk * 8 + tig + 4) * BSTR + col]);
            }
#pragma unroll
            for (int mi = 0; mi < MI; mi++)
#pragma unroll
                for (int nj = 0; nj < 8; nj++)
                    asm volatile(
                        "mma.sync.aligned.m16n8k8.row.col.f32.tf32.tf32.f32 "
                        "{%0,%1,%2,%3},{%4,%5,%6,%7},{%8,%9},{%0,%1,%2,%3};\n"
                        : "+f"(acc[mi][nj][0]), "+f"(acc[mi][nj][1]),
                          "+f"(acc[mi][nj][2]), "+f"(acc[mi][nj][3])
                        : "r"(af[mi][0]), "r"(af[mi][1]), "r"(af[mi][2]), "r"(af[mi][3]),
                          "r"(bf[nj][0]), "r"(bf[nj][1]));
        }

        if (kt + 2 < nk) loadTiles(kt + 2, (kt + 2) % 3);
        asm volatile("cp.async.commit_group;");
    }

    // ---- epilogue ----
#pragma unroll
    for (int mi = 0; mi < MI; mi++) {
        int r0 = m0 + wm + mi * 16 + g;
#pragma unroll
        for (int nj = 0; nj < 8; nj++) {
            int col = n0 + wn + nj * 8 + 2 * tig;
#pragma unroll
            for (int half = 0; half < 2; half++) {
                int rr = r0 + half * 8;
#pragma unroll
                for (int jj = 0; jj < 2; jj++) {
                    int cc = col + jj;
                    if (cc < N) {
                        float v = acc[mi][nj][half * 2 + jj];
                        if (epi != 3) v += bias[cc];
                        if (epi == 1) v = gelu_f(v);
                        long long o = (long long)rr * N + cc;
                        if (epi == 2) v += out[o];
                        out[o] = v;
                    }
                }
            }
        }
    }
}

// ---------------- tiled fp32 flash attention ----------------
// Block: 64 queries x 1 head, kv tiles of 64. 256 threads = 16(ty: 4 q) x 16(tx).
// Phase A: 4x4 scores per thread (16 FMA : 2 LDS.128). Phase B: 4x4 output cols tx*4.
__global__ void __launch_bounds__(256)
fattn_kernel(const float* __restrict__ qkv, float* __restrict__ out) {
    extern __shared__ float sm[];
    float (*sQt)[68] = (float(*)[68])(sm);              // [d][q]
    float (*sKt)[68] = (float(*)[68])(sm + 64 * 68);    // [d][kv]
    float (*sV)[68]  = (float(*)[68])(sm + 2 * 64 * 68);// [kv][d]
    float (*sP)[68]  = (float(*)[68])(sm + 3 * 64 * 68);// [q][kv]

    int tid = threadIdx.x;
    int tx = tid & 15, ty = tid >> 4;
    int qt = (int)gridDim.x - 1 - (int)blockIdx.x;  // heavy tiles first
    int h = blockIdx.y, b = blockIdx.z;
    int q0 = qt * 64;

    // load Q tile transposed (once)
    {
        int r = tid >> 4;
        int c4 = (tid & 15) * 4;
#pragma unroll
        for (int rr = 0; rr < 64; rr += 16) {
            const float* qrow = qkv + (long long)(b * Tlen + q0 + r + rr) * C3 + h * HD;
            float4 v = *(const float4*)(qrow + c4);
            sQt[c4 + 0][r + rr] = v.x;
            sQt[c4 + 1][r + rr] = v.y;
            sQt[c4 + 2][r + rr] = v.z;
            sQt[c4 + 3][r + rr] = v.w;
        }
    }

    float O[4][4] = {};
    float m[4], l[4];
#pragma unroll
    for (int i = 0; i < 4; i++) { m[i] = -INFINITY; l[i] = 0.f; }

    const float scale = 0.125f;
    int ntiles = qt + 1;

    for (int kt = 0; kt < ntiles; kt++) {
        int kv0 = kt * 64;
        __syncthreads();
        // load K (transposed) + V tile of 64 rows
        {
            int r = tid >> 4;
            int c4 = (tid & 15) * 4;
#pragma unroll
            for (int rr0 = 0; rr0 < 64; rr0 += 16) {
                int rr = r + rr0;
                const float* krow = qkv + (long long)(b * Tlen + kv0 + rr) * C3 + C + h * HD;
                float4 kv4 = *(const float4*)(krow + c4);
                sKt[c4 + 0][rr] = kv4.x;
                sKt[c4 + 1][rr] = kv4.y;
                sKt[c4 + 2][rr] = kv4.z;
                sKt[c4 + 3][rr] = kv4.w;
                const float* vrow = qkv + (long long)(b * Tlen + kv0 + rr) * C3 + 2 * C + h * HD;
                *(float4*)&sV[rr][c4] = *(const float4*)(vrow + c4);
            }
        }
        __syncthreads();

        // phase A: scores 4 q x 4 kv per thread
        float s[4][4] = {};
#pragma unroll 16
        for (int kk = 0; kk < 64; kk++) {
            float4 a = *(const float4*)&sQt[kk][ty * 4];
            float4 bv = *(const float4*)&sKt[kk][tx * 4];
            s[0][0] += a.x * bv.x; s[0][1] += a.x * bv.y; s[0][2] += a.x * bv.z; s[0][3] += a.x * bv.w;
            s[1][0] += a.y * bv.x; s[1][1] += a.y * bv.y; s[1][2] += a.y * bv.z; s[1][3] += a.y * bv.w;
            s[2][0] += a.z * bv.x; s[2][1] += a.z * bv.y; s[2][2] += a.z * bv.z; s[2][3] += a.z * bv.w;
            s[3][0] += a.w * bv.x; s[3][1] += a.w * bv.y; s[3][2] += a.w * bv.z; s[3][3] += a.w * bv.w;
        }
#pragma unroll
        for (int i = 0; i < 4; i++)
#pragma unroll
            for (int j = 0; j < 4; j++) s[i][j] *= scale;

        if (kt == qt) {   // diagonal tile: causal mask
#pragma unroll
            for (int i = 0; i < 4; i++) {
                int qg = q0 + ty * 4 + i;
#pragma unroll
                for (int j = 0; j < 4; j++)
                    if (kv0 + tx * 4 + j > qg) s[i][j] = -INFINITY;
            }
        }

        // online softmax (per q row; 16-lane reduction)
#pragma unroll
        for (int i = 0; i < 4; i++) {
            float rm = fmaxf(fmaxf(s[i][0], s[i][1]), fmaxf(s[i][2], s[i][3]));
#pragma unroll
            for (int off = 1; off < 16; off <<= 1)
                rm = fmaxf(rm, __shfl_xor_sync(0xFFFFFFFFu, rm, off));
            float mn = fmaxf(m[i], rm);
            float cs = __expf(m[i] - mn);
            float p0 = __expf(s[i][0] - mn);
            float p1 = __expf(s[i][1] - mn);
            float p2 = __expf(s[i][2] - mn);
            float p3 = __expf(s[i][3] - mn);
            float rs = (p0 + p1) + (p2 + p3);
#pragma unroll
            for (int off = 1; off < 16; off <<= 1)
                rs += __shfl_xor_sync(0xFFFFFFFFu, rs, off);
            l[i] = l[i] * cs + rs;
            m[i] = mn;
            O[i][0] *= cs; O[i][1] *= cs; O[i][2] *= cs; O[i][3] *= cs;
            sP[ty * 4 + i][tx * 4 + 0] = p0;
            sP[ty * 4 + i][tx * 4 + 1] = p1;
            sP[ty * 4 + i][tx * 4 + 2] = p2;
            sP[ty * 4 + i][tx * 4 + 3] = p3;
        }
        __syncthreads();

        // phase B: O += P @ V
#pragma unroll 8
        for (int kv = 0; kv < 64; kv++) {
            float4 v = *(const float4*)&sV[kv][tx * 4];
            float p0 = sP[ty * 4 + 0][kv];
            float p1 = sP[ty * 4 + 1][kv];
            float p2 = sP[ty * 4 + 2][kv];
            float p3 = sP[ty * 4 + 3][kv];
            O[0][0] += p0 * v.x; O[0][1] += p0 * v.y; O[0][2] += p0 * v.z; O[0][3] += p0 * v.w;
            O[1][0] += p1 * v.x; O[1][1] += p1 * v.y; O[1][2] += p1 * v.z; O[1][3] += p1 * v.w;
            O[2][0] += p2 * v.x; O[2][1] += p2 * v.y; O[2][2] += p2 * v.z; O[2][3] += p2 * v.w;
            O[3][0] += p3 * v.x; O[3][1] += p3 * v.y; O[3][2] += p3 * v.z; O[3][3] += p3 * v.w;
        }
    }

#pragma unroll
    for (int i = 0; i < 4; i++) {
        float inv = 1.f / l[i];
        float4 o4;
        o4.x = O[i][0] * inv; o4.y = O[i][1] * inv;
        o4.z = O[i][2] * inv; o4.w = O[i][3] * inv;
        float* o = out + (long long)(b * Tlen + q0 + ty * 4 + i) * C + h * HD + tx * 4;
        *(float4*)o = o4;
    }
}

// ---------------- driver ----------------
#define GEMM_SMEM(BM) (3 * ((BM) * ASTR + 16 * BSTR) * (int)sizeof(float))
#define ATTN_SMEM (4 * 64 * 68 * (int)sizeof(float))

extern "C" void kernel_launch(void* const* d_in, const int* in_sizes, int n_in,
                              void* d_out, int out_size) {
    const int*   idx      = (const int*)  d_in[0];
    const float* wte      = (const float*)d_in[1];
    const float* wpe      = (const float*)d_in[2];
    const float* ln1_w    = (const float*)d_in[3];
    const float* ln1_b    = (const float*)d_in[4];
    const float* attn_w   = (const float*)d_in[5];
    const float* attn_b   = (const float*)d_in[6];
    const float* proj_w   = (const float*)d_in[7];
    const float* proj_b   = (const float*)d_in[8];
    const float* ln2_w    = (const float*)d_in[9];
    const float* ln2_b    = (const float*)d_in[10];
    const float* fc_w     = (const float*)d_in[11];
    const float* fc_b     = (const float*)d_in[12];
    const float* fcproj_w = (const float*)d_in[13];
    const float* fcproj_b = (const float*)d_in[14];
    const float* lnf_w    = (const float*)d_in[15];
    const float* lnf_b    = (const float*)d_in[16];
    const float* lm_head  = (const float*)d_in[17];
    float* out = (float*)d_out;

    float *x, *ln, *qkv, *atty, *hbuf, *wpad;
    cudaGetSymbolAddress((void**)&x,    g_x);
    cudaGetSymbolAddress((void**)&ln,   g_ln);
    cudaGetSymbolAddress((void**)&qkv,  g_qkv);
    cudaGetSymbolAddress((void**)&atty, g_atty);
    cudaGetSymbolAddress((void**)&hbuf, g_h);
    cudaGetSymbolAddress((void**)&wpad, g_wpad);

    cudaFuncSetAttribute(tgemm_kernel<128>,
                         cudaFuncAttributeMaxDynamicSharedMemorySize, GEMM_SMEM(128));
    cudaFuncSetAttribute(tgemm_kernel<64>,
                         cudaFuncAttributeMaxDynamicSharedMemorySize, GEMM_SMEM(64));
    cudaFuncSetAttribute(fattn_kernel,
                         cudaFuncAttributeMaxDynamicSharedMemorySize, ATTN_SMEM);

    embed_kernel<<<BT, 256>>>(idx, wte, wpe, x);
    padw_kernel<<<dim3((VP + 255) / 256, C), 256>>>(lm_head, wpad);

    for (int l = 0; l < NL; l++) {
        ln_kernel<<<BT, 256>>>(x, ln1_w + l * C, ln1_b + l * C, ln);
        tgemm_kernel<128><<<dim3(C3 / 128, BT / 128), 128, GEMM_SMEM(128)>>>(
            ln, attn_w + (long long)l * C * C3, attn_b + l * C3, qkv, BT, C3, C, C3, 0);
        fattn_kernel<<<dim3(Tlen / 64, H, Bsz), 256, ATTN_SMEM>>>(qkv, atty);
        tgemm_kernel<64><<<dim3(C / 128, BT / 64), 128, GEMM_SMEM(64)>>>(
            atty, proj_w + (long long)l * C * C, proj_b + l * C, x, BT, C, C, C, 2);
        ln_kernel<<<BT, 256>>>(x, ln2_w + l * C, ln2_b + l * C, ln);
        tgemm_kernel<128><<<dim3(C4 / 128, BT / 128), 128, GEMM_SMEM(128)>>>(
            ln, fc_w + (long long)l * C * C4, fc_b + l * C4, hbuf, BT, C4, C, C4, 1);
        tgemm_kernel<64><<<dim3(C / 128, BT / 64), 128, GEMM_SMEM(64)>>>(
            hbuf, fcproj_w + (long long)l * C4 * C, fcproj_b + l * C, x, BT, C, C4, C, 2);
    }

    ln_kernel<<<BT, 256>>>(x, lnf_w, lnf_b, ln);
    tgemm_kernel<128><<<dim3(VP / 128, BT / 128), 128, GEMM_SMEM(128)>>>(
        ln, wpad, (const float*)nullptr, out, BT, V, C, VP, 3);
}